// round 17
// baseline (speedup 1.0000x reference)
#include <cuda_runtime.h>
#include <cuda_fp16.h>
#include <math.h>
#include <stdint.h>

// ---------------- problem dims ----------------
#define BSZ     64
#define TSEQ    64
#define EDIM    512
#define DMODEL  1024
#define DINNER  2048
#define NTOK    (BSZ*TSEQ)       // 4096
#define DSTATE  16
#define DTRANK  64
#define PROJW   96

// ---------------- scratch (device globals, zero-initialized at load) ----------------
__device__ float g_proj [NTOK * PROJW];
__device__ float g_projp[2 * NTOK * PROJW];
__device__ __half g_z2  [NTOK * DINNER];
__device__ __half g_dt2 [NTOK * DINNER];
__device__ __half g_Ax   [NTOK * 2 * DMODEL];        // split2 input
__device__ __half g_Bwin [2 * DINNER * DMODEL];      // single (GEMM wraps K)
__device__ __half g_Axc  [NTOK * DINNER];            // xc single
__device__ __half g_Bwx  [128 * DINNER];             // rows 96..127 = 0
__device__ __half g_Adt  [NTOK * 2 * DTRANK];        // dt_raw split2
__device__ __half g_Bwdt [DINNER * DTRANK];          // single (GEMM wraps K)
__device__ __half g_Ay   [NTOK * DINNER];
__device__ __half g_Bwout[DMODEL * DINNER];
__device__ __half g_Af   [NTOK * DMODEL];
__device__ __half g_Bw1  [512 * DMODEL];
__device__ __half g_Ah1  [NTOK * 512];
__device__ __half g_Bw2  [256 * 512];

// ---------------- MUFU transcendentals ----------------
__device__ __forceinline__ float ex2f(float x) { float y; asm("ex2.approx.f32 %0, %1;" : "=f"(y) : "f"(x)); return y; }
__device__ __forceinline__ float lg2f(float x) { float y; asm("lg2.approx.f32 %0, %1;" : "=f"(y) : "f"(x)); return y; }
__device__ __forceinline__ float rcpf(float x) { float y; asm("rcp.approx.f32 %0, %1;" : "=f"(y) : "f"(x)); return y; }
#define LOG2E 1.4426950408889634f
#define LN2   0.6931471805599453f

__device__ __forceinline__ float softplus_f(float x) {
    if (x > 15.0f) return x;
    return LN2 * lg2f(1.0f + ex2f(LOG2E * x));
}
__device__ __forceinline__ float silu_f(float x) {
    return x * rcpf(1.0f + ex2f(-LOG2E * x));
}

// ---------------- PTX helpers ----------------
__device__ __forceinline__ uint32_t smem_u32(const void* p) {
    uint32_t a;
    asm("{ .reg .u64 t; cvta.to.shared.u64 t, %1; cvt.u32.u64 %0, t; }" : "=r"(a) : "l"(p));
    return a;
}
#define SWZ(off) ((off) ^ (((off) >> 3) & 0x70))

#define CP16(dst, src) asm volatile("cp.async.cg.shared.global [%0], [%1], 16;\n" :: "r"(dst), "l"(src) : "memory")
#define CP_COMMIT()    asm volatile("cp.async.commit_group;\n" ::: "memory")
#define CP_WAIT(n)     asm volatile("cp.async.wait_group %0;\n" :: "n"(n) : "memory")

#define LDSM_X4(r0, r1, r2, r3, addr) \
    asm volatile("ldmatrix.sync.aligned.m8n8.x4.shared.b16 {%0,%1,%2,%3}, [%4];" \
        : "=r"(r0), "=r"(r1), "=r"(r2), "=r"(r3) : "r"(addr))

#define MMA_F16(c0, c1, c2, c3, a0, a1, a2, a3, b0, b1) \
    asm volatile("mma.sync.aligned.m16n8k16.row.col.f32.f16.f16.f32 " \
        "{%0,%1,%2,%3}, {%4,%5,%6,%7}, {%8,%9}, {%0,%1,%2,%3};" \
        : "+f"(c0), "+f"(c1), "+f"(c2), "+f"(c3) \
        : "r"(a0), "r"(a1), "r"(a2), "r"(a3), "r"(b0), "r"(b1))

__device__ __forceinline__ void split_f16(float v, __half& hi, __half& lo) {
    hi = __float2half_rn(v);
    lo = __float2half_rn(v - __half2float(hi));
}

// ======================================================================
// BIG GEMM. WRAPB: B buffer is single-width (K2/2); loader wraps k so the
// second K-half re-reads the same bytes (L2 hits).
// MODE 0: fp32 out. MODE 2 (BMT=64, conv-fuse). MODE 3: single fp16 out.
// ======================================================================
template<int BMT, int ACT, int MODE, bool WRAPB>
__global__ void __launch_bounds__(128, (BMT == 64) ? 3 : 2) tgbig_k(
    const __half* __restrict__ A,
    const __half* __restrict__ B,
    const float* __restrict__ bias,
    float* __restrict__ Cout,
    __half* __restrict__ Cs,
    __half* __restrict__ Zs,
    int M, int N, int K2,
    const float* __restrict__ cw, const float* __restrict__ cb)
{
    constexpr int MT    = BMT / 32;
    constexpr int STAGE = (BMT + 128) * 128;
    extern __shared__ char dsm[];
    const uint32_t base = (smem_u32(dsm) + 1023u) & ~1023u;
    const uint32_t pad  = base - smem_u32(dsm);

    const int tid  = threadIdx.x;
    const int wid  = tid >> 5;
    const int lane = tid & 31;
    const int bm   = blockIdx.y * BMT;
    const int bn   = blockIdx.x * 128;

    const int wm = wid & 1;
    const int wn = wid >> 1;

    const uint32_t aRow  = (uint32_t)(wm * (BMT / 2) + (lane & 15));
    const uint32_t aKsel = (uint32_t)(((lane >> 4) & 1) * 16);
    const uint32_t bRow  = (uint32_t)(wn * 64 + (lane & 7) + ((lane >> 4) & 1) * 8);
    const uint32_t bKsel = (uint32_t)(((lane >> 3) & 1) * 16);

    float c[MT][8][4];
    #pragma unroll
    for (int mt = 0; mt < MT; mt++)
        #pragma unroll
        for (int nt = 0; nt < 8; nt++)
            #pragma unroll
            for (int r = 0; r < 4; r++) c[mt][nt][r] = 0.0f;

    const int S  = K2 / 64;
    const int Kb = WRAPB ? (K2 >> 1) : K2;        // physical B row stride

    auto load_stage = [&](uint32_t abase, int k0) {
        const uint32_t bbase = abase + BMT * 128;
        #pragma unroll
        for (int i = 0; i < (BMT * 8) / 128; i++) {
            int cc = tid + i * 128;
            int row = cc >> 3, ch = cc & 7;
            uint32_t dst = abase + SWZ((uint32_t)(row * 128 + ch * 16));
            CP16(dst, A + (size_t)(bm + row) * K2 + k0 + ch * 8);
        }
        const int kb = (WRAPB && k0 >= Kb) ? (k0 - Kb) : k0;
        #pragma unroll
        for (int i = 0; i < 8; i++) {
            int cc = tid + i * 128;
            int row = cc >> 3, ch = cc & 7;
            uint32_t dst = bbase + SWZ((uint32_t)(row * 128 + ch * 16));
            CP16(dst, B + (size_t)(bn + row) * Kb + kb + ch * 8);
        }
        CP_COMMIT();
    };

    load_stage(base,         0);
    load_stage(base + STAGE, 64);
    if (S > 2) load_stage(base + 2 * STAGE, 128);

    for (int s = 0; s < S; s++) {
        if (s + 3 <= S)      { CP_WAIT(2); }
        else if (s + 2 == S) { CP_WAIT(1); }
        else                 { CP_WAIT(0); }
        __syncthreads();

        const int buf = s % 3;
        const uint32_t ab = base + (uint32_t)buf * STAGE;
        const uint32_t bb = ab + BMT * 128;

        #pragma unroll
        for (int ks = 0; ks < 4; ks++) {
            uint32_t a[MT][4];
            #pragma unroll
            for (int mt = 0; mt < MT; mt++) {
                uint32_t addr = ab + SWZ((aRow + mt * 16) * 128 + (uint32_t)ks * 32 + aKsel);
                LDSM_X4(a[mt][0], a[mt][1], a[mt][2], a[mt][3], addr);
            }
            #pragma unroll
            for (int ntp = 0; ntp < 4; ntp++) {
                uint32_t b0, b1, b2, b3;
                uint32_t addr = bb + SWZ((bRow + ntp * 16) * 128 + (uint32_t)ks * 32 + bKsel);
                LDSM_X4(b0, b1, b2, b3, addr);
                #pragma unroll
                for (int mt = 0; mt < MT; mt++) {
                    MMA_F16(c[mt][2 * ntp][0], c[mt][2 * ntp][1],
                            c[mt][2 * ntp][2], c[mt][2 * ntp][3],
                            a[mt][0], a[mt][1], a[mt][2], a[mt][3], b0, b1);
                    MMA_F16(c[mt][2 * ntp + 1][0], c[mt][2 * ntp + 1][1],
                            c[mt][2 * ntp + 1][2], c[mt][2 * ntp + 1][3],
                            a[mt][0], a[mt][1], a[mt][2], a[mt][3], b2, b3);
                }
            }
        }

        __syncthreads();
        if (s + 3 < S)
            load_stage(base + (uint32_t)buf * STAGE, (s + 3) * 64);
    }

    const int g    = lane >> 2;
    const int tcol = (lane & 3) * 2;

    if (MODE == 2) {
        const bool is_xi = (bn < DINNER);
        if (is_xi) {
            float* sc = (float*)(dsm + pad);
            #pragma unroll
            for (int mt = 0; mt < MT; mt++)
                #pragma unroll
                for (int half = 0; half < 2; half++) {
                    const int rl = wm * (BMT / 2) + mt * 16 + half * 8 + g;
                    #pragma unroll
                    for (int nt = 0; nt < 8; nt++) {
                        const int cl = wn * 64 + nt * 8 + tcol;
                        *(float2*)&sc[rl * 128 + cl] =
                            make_float2(c[mt][nt][half * 2], c[mt][nt][half * 2 + 1]);
                    }
                }
            __syncthreads();
            const int d  = bn + tid;
            const float w0 = cw[d * 4 + 0], w1 = cw[d * 4 + 1];
            const float w2 = cw[d * 4 + 2], w3 = cw[d * 4 + 3];
            const float cbias = cb[d];
            float x0 = 0.f, x1 = 0.f, x2 = 0.f;
            for (int t = 0; t < TSEQ; t++) {
                const float x3 = sc[t * 128 + tid];
                const float v  = fmaf(w3, x3, fmaf(w2, x2, fmaf(w1, x1, w0 * x0))) + cbias;
                Cs[(size_t)(bm + t) * DINNER + d] = __float2half_rn(silu_f(v));
                x0 = x1; x1 = x2; x2 = x3;
            }
        } else {
            const int zc = bn - DINNER;
            #pragma unroll
            for (int mt = 0; mt < MT; mt++)
                #pragma unroll
                for (int half = 0; half < 2; half++) {
                    const int row = bm + wm * (BMT / 2) + mt * 16 + half * 8 + g;
                    #pragma unroll
                    for (int nt = 0; nt < 8; nt++) {
                        const int col = zc + wn * 64 + nt * 8 + tcol;
                        *(__half2*)(Zs + (size_t)row * DINNER + col) =
                            __halves2half2(__float2half_rn(c[mt][nt][half * 2]),
                                           __float2half_rn(c[mt][nt][half * 2 + 1]));
                    }
                }
        }
        return;
    }

    #pragma unroll
    for (int mt = 0; mt < MT; mt++) {
        #pragma unroll
        for (int half = 0; half < 2; half++) {
            const int row = bm + wm * (BMT / 2) + mt * 16 + half * 8 + g;
            #pragma unroll
            for (int nt = 0; nt < 8; nt++) {
                const int col = bn + wn * 64 + nt * 8 + tcol;
                float v0 = c[mt][nt][half * 2 + 0];
                float v1 = c[mt][nt][half * 2 + 1];
                if (bias) { v0 += __ldg(&bias[col]); v1 += __ldg(&bias[col + 1]); }
                if (ACT == 2) { v0 = softplus_f(v0); v1 = softplus_f(v1); }
                if (MODE == 3) {
                    *(__half2*)(Cs + (size_t)row * N + col) =
                        __halves2half2(__float2half_rn(v0), __float2half_rn(v1));
                } else {
                    *(float2*)(Cout + (size_t)row * N + col) = make_float2(v0, v1);
                }
            }
        }
    }
}

// ======================================================================
// SMALL GEMM (unchanged structure)
// ======================================================================
template<int BM_, bool SPLITK, int ACT, int OUT>
__global__ void __launch_bounds__(256, 2) tgsm_k(
    const __half* __restrict__ A,
    const __half* __restrict__ B,
    const float* __restrict__ bias,
    float* __restrict__ Cout,
    __half* __restrict__ Cs,
    int M, int Nout, int K2, int kchunk)
{
    constexpr int NWM = BM_ / 32;
    constexpr int NWN = 8 / NWM;
    constexpr int WNW = 128 / NWN;
    constexpr int NT  = WNW / 8;
    constexpr int STAGE = (BM_ + 128) * 128;
    extern __shared__ char dsm[];
    const uint32_t base = (smem_u32(dsm) + 1023u) & ~1023u;

    const int tid  = threadIdx.x;
    const int wid  = tid >> 5;
    const int lane = tid & 31;
    const int bm   = blockIdx.y * BM_;
    const int bn   = blockIdx.x * 128;

    const int kbeg = SPLITK ? blockIdx.z * kchunk : 0;
    const int S    = (SPLITK ? kchunk : K2) / 64;

    float* Cpart = SPLITK ? (Cout + (size_t)blockIdx.z * M * Nout) : Cout;

    const int wm = wid % NWM;
    const int wn = wid / NWM;

    const uint32_t aRow  = (uint32_t)(wm * 32 + (lane & 15));
    const uint32_t aKsel = (uint32_t)(((lane >> 4) & 1) * 16);
    const uint32_t bRow  = (uint32_t)(wn * WNW + (lane & 7) + ((lane >> 4) & 1) * 8);
    const uint32_t bKsel = (uint32_t)(((lane >> 3) & 1) * 16);

    float c[2][NT][4];
    #pragma unroll
    for (int mt = 0; mt < 2; mt++)
        #pragma unroll
        for (int nt = 0; nt < NT; nt++)
            #pragma unroll
            for (int r = 0; r < 4; r++) c[mt][nt][r] = 0.0f;

    auto load_stage = [&](uint32_t abase, int k0) {
        const uint32_t bbase = abase + BM_ * 128;
        #pragma unroll
        for (int i = 0; i < (BM_ * 8) / 256; i++) {
            int cc = tid + i * 256;
            int row = cc >> 3, ch = cc & 7;
            uint32_t dst = abase + SWZ((uint32_t)(row * 128 + ch * 16));
            CP16(dst, A + (size_t)(bm + row) * K2 + k0 + ch * 8);
        }
        #pragma unroll
        for (int i = 0; i < 4; i++) {
            int cc = tid + i * 256;
            int row = cc >> 3, ch = cc & 7;
            uint32_t dst = bbase + SWZ((uint32_t)(row * 128 + ch * 16));
            CP16(dst, B + (size_t)(bn + row) * K2 + k0 + ch * 8);
        }
        CP_COMMIT();
    };

    load_stage(base,         kbeg);
    load_stage(base + STAGE, kbeg + 64);
    if (S > 2) load_stage(base + 2 * STAGE, kbeg + 128);

    for (int s = 0; s < S; s++) {
        if (s + 3 <= S)      { CP_WAIT(2); }
        else if (s + 2 == S) { CP_WAIT(1); }
        else                 { CP_WAIT(0); }
        __syncthreads();

        const int buf = s % 3;
        const uint32_t ab = base + (uint32_t)buf * STAGE;
        const uint32_t bb = ab + BM_ * 128;

        #pragma unroll
        for (int ks = 0; ks < 4; ks++) {
            uint32_t a[2][4], b[NT / 2][4];
            #pragma unroll
            for (int mt = 0; mt < 2; mt++) {
                uint32_t addr = ab + SWZ((aRow + mt * 16) * 128 + (uint32_t)ks * 32 + aKsel);
                LDSM_X4(a[mt][0], a[mt][1], a[mt][2], a[mt][3], addr);
            }
            #pragma unroll
            for (int ntp = 0; ntp < NT / 2; ntp++) {
                uint32_t addr = bb + SWZ((bRow + ntp * 16) * 128 + (uint32_t)ks * 32 + bKsel);
                LDSM_X4(b[ntp][0], b[ntp][1], b[ntp][2], b[ntp][3], addr);
            }
            #pragma unroll
            for (int mt = 0; mt < 2; mt++)
                #pragma unroll
                for (int nt = 0; nt < NT; nt++) {
                    const int ntp = nt >> 1, hi = nt & 1;
                    MMA_F16(c[mt][nt][0], c[mt][nt][1], c[mt][nt][2], c[mt][nt][3],
                            a[mt][0], a[mt][1], a[mt][2], a[mt][3],
                            b[ntp][hi * 2], b[ntp][hi * 2 + 1]);
                }
        }

        __syncthreads();
        if (s + 3 < S)
            load_stage(base + (uint32_t)buf * STAGE, kbeg + (s + 3) * 64);
    }

    const int g    = lane >> 2;
    const int tcol = (lane & 3) * 2;
    #pragma unroll
    for (int mt = 0; mt < 2; mt++) {
        #pragma unroll
        for (int half = 0; half < 2; half++) {
            const int row = bm + wm * 32 + mt * 16 + half * 8 + g;
            #pragma unroll
            for (int nt = 0; nt < NT; nt++) {
                const int col = bn + wn * WNW + nt * 8 + tcol;
                if (col >= Nout) continue;
                float v0 = c[mt][nt][half * 2 + 0];
                float v1 = c[mt][nt][half * 2 + 1];
                if (SPLITK) {
                    if (col + 1 < Nout) {
                        *(float2*)(Cpart + (size_t)row * Nout + col) = make_float2(v0, v1);
                    } else {
                        Cpart[(size_t)row * Nout + col] = v0;
                    }
                } else {
                    if (bias) { v0 += __ldg(&bias[col]); v1 += __ldg(&bias[col + 1]); }
                    if (ACT == 1) { v0 = fmaxf(v0, 0.0f); v1 = fmaxf(v1, 0.0f); }
                    if (OUT == 2) {
                        *(__half2*)(Cs + (size_t)row * Nout + col) =
                            __halves2half2(__float2half_rn(v0), __float2half_rn(v1));
                    } else {
                        *(float2*)(Cout + (size_t)row * Nout + col) = make_float2(v0, v1);
                    }
                }
            }
        }
    }
}

// ======================================================================
// FINAL GEMM + HEAD fused (unchanged from R16)
// ======================================================================
__global__ void __launch_bounds__(256, 1) tgfinal_k(
    const __half* __restrict__ A,
    const __half* __restrict__ B,
    const float* __restrict__ b2,
    const float* __restrict__ W3,
    const float* __restrict__ b3,
    float* __restrict__ out)
{
    constexpr int K2 = 512, S = 8;
    constexpr int STAGE = (64 + 256) * 128;
    extern __shared__ char dsm[];
    const uint32_t base = (smem_u32(dsm) + 1023u) & ~1023u;
    const uint32_t pad  = base - smem_u32(dsm);

    const int tid  = threadIdx.x;
    const int wid  = tid >> 5;
    const int lane = tid & 31;
    const int bm   = blockIdx.y * 64;

    const int wm = wid & 1;
    const int wn = wid >> 1;

    const uint32_t aRow  = (uint32_t)(wm * 32 + (lane & 15));
    const uint32_t aKsel = (uint32_t)(((lane >> 4) & 1) * 16);
    const uint32_t bRow  = (uint32_t)(wn * 64 + (lane & 7) + ((lane >> 4) & 1) * 8);
    const uint32_t bKsel = (uint32_t)(((lane >> 3) & 1) * 16);

    float c[2][8][4];
    #pragma unroll
    for (int mt = 0; mt < 2; mt++)
        #pragma unroll
        for (int nt = 0; nt < 8; nt++)
            #pragma unroll
            for (int r = 0; r < 4; r++) c[mt][nt][r] = 0.0f;

    auto load_stage = [&](uint32_t abase, int k0) {
        const uint32_t bbase = abase + 64 * 128;
        #pragma unroll
        for (int i = 0; i < 2; i++) {
            int cc = tid + i * 256;
            int row = cc >> 3, ch = cc & 7;
            uint32_t dst = abase + SWZ((uint32_t)(row * 128 + ch * 16));
            CP16(dst, A + (size_t)(bm + row) * K2 + k0 + ch * 8);
        }
        #pragma unroll
        for (int i = 0; i < 8; i++) {
            int cc = tid + i * 256;
            int row = cc >> 3, ch = cc & 7;
            uint32_t dst = bbase + SWZ((uint32_t)(row * 128 + ch * 16));
            CP16(dst, B + (size_t)row * K2 + k0 + ch * 8);
        }
        CP_COMMIT();
    };

    load_stage(base,             0);
    load_stage(base + STAGE,     64);
    load_stage(base + 2 * STAGE, 128);

    for (int s = 0; s < S; s++) {
        if (s + 3 <= S)      { CP_WAIT(2); }
        else if (s + 2 == S) { CP_WAIT(1); }
        else                 { CP_WAIT(0); }
        __syncthreads();

        const int buf = s % 3;
        const uint32_t ab = base + (uint32_t)buf * STAGE;
        const uint32_t bb = ab + 64 * 128;

        #pragma unroll
        for (int ks = 0; ks < 4; ks++) {
            uint32_t a[2][4];
            #pragma unroll
            for (int mt = 0; mt < 2; mt++) {
                uint32_t addr = ab + SWZ((aRow + mt * 16) * 128 + (uint32_t)ks * 32 + aKsel);
                LDSM_X4(a[mt][0], a[mt][1], a[mt][2], a[mt][3], addr);
            }
            #pragma unroll
            for (int ntp = 0; ntp < 4; ntp++) {
                uint32_t b0, b1, b2r, b3r;
                uint32_t addr = bb + SWZ((bRow + ntp * 16) * 128 + (uint32_t)ks * 32 + bKsel);
                LDSM_X4(b0, b1, b2r, b3r, addr);
                #pragma unroll
                for (int mt = 0; mt < 2; mt++) {
                    MMA_F16(c[mt][2 * ntp][0], c[mt][2 * ntp][1],
                            c[mt][2 * ntp][2], c[mt][2 * ntp][3],
                            a[mt][0], a[mt][1], a[mt][2], a[mt][3], b0, b1);
                    MMA_F16(c[mt][2 * ntp + 1][0], c[mt][2 * ntp + 1][1],
                            c[mt][2 * ntp + 1][2], c[mt][2 * ntp + 1][3],
                            a[mt][0], a[mt][1], a[mt][2], a[mt][3], b2r, b3r);
                }
            }
        }

        __syncthreads();
        if (s + 3 < S)
            load_stage(base + (uint32_t)buf * STAGE, (s + 3) * 64);
    }

    float* sh2 = (float*)(dsm + pad);
    float* sW3 = (float*)(dsm + pad + 65536);
    const int g    = lane >> 2;
    const int tcol = (lane & 3) * 2;
    #pragma unroll
    for (int mt = 0; mt < 2; mt++) {
        #pragma unroll
        for (int half = 0; half < 2; half++) {
            const int rl = wm * 32 + mt * 16 + half * 8 + g;
            #pragma unroll
            for (int nt = 0; nt < 8; nt++) {
                const int col = wn * 64 + nt * 8 + tcol;
                float v0 = fmaxf(c[mt][nt][half * 2 + 0] + __ldg(&b2[col]), 0.0f);
                float v1 = fmaxf(c[mt][nt][half * 2 + 1] + __ldg(&b2[col + 1]), 0.0f);
                *(float2*)&sh2[rl * 256 + col] = make_float2(v0, v1);
            }
        }
    }
    for (int i = tid; i < 256 * 6; i += 256) sW3[i] = W3[i];
    __syncthreads();

    #pragma unroll
    for (int rr = 0; rr < 8; rr++) {
        const int r = wid * 8 + rr;
        float acc[6] = {0.f, 0.f, 0.f, 0.f, 0.f, 0.f};
        #pragma unroll
        for (int kk = 0; kk < 8; kk++) {
            const int k = kk * 32 + lane;
            const float v = sh2[r * 256 + k];
            #pragma unroll
            for (int j = 0; j < 6; j++) acc[j] = fmaf(v, sW3[k * 6 + j], acc[j]);
        }
        #pragma unroll
        for (int j = 0; j < 6; j++) {
            #pragma unroll
            for (int o = 16; o > 0; o >>= 1)
                acc[j] += __shfl_xor_sync(0xffffffffu, acc[j], o);
        }
        if (lane == 0) {
            #pragma unroll
            for (int j = 0; j < 6; j++)
                out[(size_t)(bm + r) * 6 + j] = acc[j] + b3[j];
        }
    }
}

// ---------------- batched prep: 6 weight transposes + concat ----------------
struct WtJobs {
    const float* W[6];
    __half*      out[7];
    int          K[7];
    int          N[7];
    int          off[8];
};

__global__ void prep_all(WtJobs j, const float* __restrict__ sp,
                         const float* __restrict__ te) {
    __shared__ float s[32][33];
    const int b = blockIdx.x;
    int job = 0;
    #pragma unroll
    for (int q = 0; q < 6; q++) if (b >= j.off[q + 1]) job = q + 1;
    const int rel = b - j.off[job];
    const int tx = threadIdx.x, ty = threadIdx.y;

    if (job == 6) {
        const int tilesN = DMODEL / 32;
        const int n0 = (rel % tilesN) * 32;
        const int k0 = (rel / tilesN) * 32;
        __half* ax = j.out[6];
        #pragma unroll
        for (int i = 0; i < 4; i++) {
            const int row = k0 + ty + 8 * i;
            const int c   = n0 + tx;
            float v = (c < EDIM) ? sp[(size_t)row * EDIM + c]
                                 : te[(size_t)row * EDIM + (c - EDIM)];
            __half hi, lo; split_f16(v, hi, lo);
            size_t bb = (size_t)row * (2 * DMODEL);
            ax[bb + c]          = hi;
            ax[bb + DMODEL + c] = lo;
        }
        return;
    }

    const float* W = j.W[job];
    __half* outp   = j.out[job];
    const int K = j.K[job], N = j.N[job];
    const int tilesN = N >> 5;
    const int n0 = (rel % tilesN) * 32;
    const int k0 = (rel / tilesN) * 32;

    #pragma unroll
    for (int i = 0; i < 4; i++)
        s[ty + 8 * i][tx] = W[(size_t)(k0 + ty + 8 * i) * N + n0 + tx];
    __syncthreads();
    #pragma unroll
    for (int i = 0; i < 4; i++) {
        int n = n0 + ty + 8 * i;
        float v = s[tx][ty + 8 * i];
        outp[(size_t)n * K + k0 + tx] = __float2half_rn(v);
    }
}

// ---------------- reduce 2 partials -> proj fp32 + dt_raw split2 ----------------
__global__ void reduce_dtraw_kernel(const float* __restrict__ projp,
                                    float* __restrict__ proj,
                                    __half* __restrict__ adt) {
    int i = blockIdx.x * 256 + threadIdx.x;
    if (i < NTOK * PROJW) {
        float v = projp[i] + projp[i + NTOK * PROJW];
        proj[i] = v;
        int r = i / PROJW, c = i - r * PROJW;
        if (c < DTRANK) {
            __half hi, lo; split_f16(v, hi, lo);
            size_t b = (size_t)r * (2 * DTRANK);
            adt[b + c]          = hi;
            adt[b + DTRANK + c] = lo;
        }
    }
}

// ---------------- selective scan: 2 channels/thread (half2 loads) ----------------
__global__ void __launch_bounds__(512) scan_kernel(
    const float* __restrict__ proj,
    const __half* __restrict__ dt2,
    const __half* __restrict__ xc2,
    const __half* __restrict__ z2,
    const float* __restrict__ A_log,
    const float* __restrict__ D_skip,
    __half* __restrict__ y2)
{
    const int b  = blockIdx.y;
    const int d0 = (blockIdx.x * 512 + threadIdx.x) * 2;

    __shared__ float sBC[TSEQ][32];
    for (int i = threadIdx.x; i < TSEQ * 32; i += 512) {
        int t = i >> 5, c = i & 31;
        sBC[t][c] = proj[((size_t)(b * TSEQ + t)) * PROJW + DTRANK + c];
    }
    __syncthreads();

    float A2[2][DSTATE];
    #pragma unroll
    for (int p = 0; p < 2; p++)
        #pragma unroll
        for (int n = 0; n < DSTATE; n++)
            A2[p][n] = -ex2f(A_log[(size_t)(d0 + p) * DSTATE + n] * LOG2E) * LOG2E;
    const float Dv0 = D_skip[d0], Dv1 = D_skip[d0 + 1];

    float h[2][DSTATE];
    #pragma unroll
    for (int p = 0; p < 2; p++)
        #pragma unroll
        for (int n = 0; n < DSTATE; n++) h[p][n] = 0.0f;

    const size_t rbase = (size_t)b * TSEQ;
    for (int t = 0; t < TSEQ; t++) {
        const size_t row = rbase + t;
        const float2 dtv = __half22float2(*(const __half2*)(dt2 + row * DINNER + d0));
        const float2 xv  = __half22float2(*(const __half2*)(xc2 + row * DINNER + d0));
        const float2 zv  = __half22float2(*(const __half2*)(z2  + row * DINNER + d0));
        const float dtx0 = dtv.x * xv.x, dtx1 = dtv.y * xv.y;
        float yv0 = 0.0f, yv1 = 0.0f;
        #pragma unroll
        for (int n = 0; n < DSTATE; n++) {
            const float Bn = sBC[t][n], Cn = sBC[t][16 + n];
            const float dA0 = ex2f(dtv.x * A2[0][n]);
            h[0][n] = fmaf(dA0, h[0][n], dtx0 * Bn);
            yv0     = fmaf(h[0][n], Cn, yv0);
            const float dA1 = ex2f(dtv.y * A2[1][n]);
            h[1][n] = fmaf(dA1, h[1][n], dtx1 * Bn);
            yv1     = fmaf(h[1][n], Cn, yv1);
        }
        yv0 = fmaf(xv.x, Dv0, yv0);
        yv1 = fmaf(xv.y, Dv1, yv1);
        const float v0 = yv0 * zv.x * rcpf(1.0f + ex2f(-LOG2E * zv.x));
        const float v1 = yv1 * zv.y * rcpf(1.0f + ex2f(-LOG2E * zv.y));
        *(__half2*)(y2 + row * DINNER + d0) =
            __halves2half2(__float2half_rn(v0), __float2half_rn(v1));
    }
}

// ---------------- launch ----------------
extern "C" void kernel_launch(void* const* d_in, const int* in_sizes, int n_in,
                              void* d_out, int out_size)
{
    const float* spatial  = (const float*)d_in[0];
    const float* temporal = (const float*)d_in[1];
    const float* W_in     = (const float*)d_in[2];
    const float* conv_w   = (const float*)d_in[3];
    const float* conv_b   = (const float*)d_in[4];
    const float* W_x      = (const float*)d_in[5];
    const float* W_dt     = (const float*)d_in[6];
    const float* b_dt     = (const float*)d_in[7];
    const float* A_log    = (const float*)d_in[8];
    const float* D_skip   = (const float*)d_in[9];
    const float* W_out    = (const float*)d_in[10];
    const float* W1       = (const float*)d_in[11];
    const float* b1       = (const float*)d_in[12];
    const float* W2       = (const float*)d_in[13];
    const float* b2       = (const float*)d_in[14];
    const float* W3       = (const float*)d_in[15];
    const float* b3       = (const float*)d_in[16];
    float* out = (float*)d_out;

    float *pproj, *pprojp;
    __half *pz2, *pdt2;
    __half *pAx, *pBwin, *pAxc, *pBwx, *pAdt, *pBwdt, *pAy, *pBwout,
           *pAf, *pBw1, *pAh1, *pBw2;
    cudaGetSymbolAddress((void**)&pproj,  g_proj);
    cudaGetSymbolAddress((void**)&pprojp, g_projp);
    cudaGetSymbolAddress((void**)&pz2,    g_z2);
    cudaGetSymbolAddress((void**)&pdt2,   g_dt2);
    cudaGetSymbolAddress((void**)&pAx,    g_Ax);
    cudaGetSymbolAddress((void**)&pBwin,  g_Bwin);
    cudaGetSymbolAddress((void**)&pAxc,   g_Axc);
    cudaGetSymbolAddress((void**)&pBwx,   g_Bwx);
    cudaGetSymbolAddress((void**)&pAdt,   g_Adt);
    cudaGetSymbolAddress((void**)&pBwdt,  g_Bwdt);
    cudaGetSymbolAddress((void**)&pAy,    g_Ay);
    cudaGetSymbolAddress((void**)&pBwout, g_Bwout);
    cudaGetSymbolAddress((void**)&pAf,    g_Af);
    cudaGetSymbolAddress((void**)&pBw1,   g_Bw1);
    cudaGetSymbolAddress((void**)&pAh1,   g_Ah1);
    cudaGetSymbolAddress((void**)&pBw2,   g_Bw2);

    const int SMEM_B128 = 3 * (128 + 128) * 128 + 1024;   // 99328
    const int SMEM_B64  = 3 * (64  + 128) * 128 + 1024;   // 74752
    const int SMEM_FIN  = 3 * (64  + 256) * 128 + 1024;   // 123904
    cudaFuncSetAttribute(tgbig_k<64,  0, 2, true>,  cudaFuncAttributeMaxDynamicSharedMemorySize, SMEM_B64);
    cudaFuncSetAttribute(tgbig_k<128, 2, 3, true>,  cudaFuncAttributeMaxDynamicSharedMemorySize, SMEM_B128);
    cudaFuncSetAttribute(tgbig_k<128, 0, 3, false>, cudaFuncAttributeMaxDynamicSharedMemorySize, SMEM_B128);
    cudaFuncSetAttribute(tgsm_k<64, true,  0, 0>, cudaFuncAttributeMaxDynamicSharedMemorySize, SMEM_B64);
    cudaFuncSetAttribute(tgsm_k<64, false, 1, 2>, cudaFuncAttributeMaxDynamicSharedMemorySize, SMEM_B64);
    cudaFuncSetAttribute(tgfinal_k, cudaFuncAttributeMaxDynamicSharedMemorySize, SMEM_FIN);

    // prep job table: 6 single-width weight jobs + concat (job 6)
    WtJobs wj;
    const float* Ws[6]  = { W_in, W_x, W_dt, W_out, W1, W2 };
    __half* Os[7]       = { pBwin, pBwx, pBwdt, pBwout, pBw1, pBw2, pAx };
    const int Ks[7]     = { DMODEL, DINNER, DTRANK, DINNER, DMODEL, 512, NTOK };
    const int Ns[7]     = { 2 * DINNER, PROJW, DINNER, DMODEL, 512, 256, DMODEL };
    int acc = 0;
    for (int q = 0; q < 7; q++) {
        if (q < 6) wj.W[q] = Ws[q];
        wj.out[q] = Os[q]; wj.K[q] = Ks[q]; wj.N[q] = Ns[q];
        wj.off[q] = acc;
        acc += (Ns[q] / 32) * (Ks[q] / 32);
    }
    wj.off[7] = acc;

    // 0) prep: weight transposes (single width) + concat/split2
    prep_all<<<acc, dim3(32, 8)>>>(wj, spatial, temporal);
    // 1) G1 (conv-fused, WRAPB): xi -> conv+silu -> xc; z -> fp16 z2
    tgbig_k<64, 0, 2, true><<<dim3(4096 / 128, NTOK / 64), 128, SMEM_B64>>>(
        pAx, pBwin, nullptr, nullptr, pAxc, pz2, NTOK, 4096, 2 * DMODEL, conv_w, conv_b);
    // 2) Gx: proj partials (split-K x2, K=DINNER)
    tgsm_k<64, true, 0, 0><<<dim3(1, NTOK / 64, 2), 256, SMEM_B64>>>(
        pAxc, pBwx, nullptr, pprojp, nullptr, NTOK, PROJW, DINNER, DINNER / 2);
    // 3) reduce partials -> proj + dt_raw split2
    reduce_dtraw_kernel<<<(NTOK * PROJW + 255) / 256, 256>>>(pprojp, pproj, pAdt);
    // 4) G3 (WRAPB): dt = softplus(dt_raw @ W_dt + b_dt) -> fp16 dt2
    tgbig_k<128, 2, 3, true><<<dim3(DINNER / 128, NTOK / 128), 128, SMEM_B128>>>(
        pAdt, pBwdt, b_dt, nullptr, pdt2, nullptr, NTOK, DINNER, 2 * DTRANK, nullptr, nullptr);
    // 5) scan -> y single fp16 (2 ch/thread)
    scan_kernel<<<dim3(DINNER / 1024, BSZ), 512>>>(pproj, pdt2, pAxc, pz2, A_log, D_skip, pAy);
    // 6) G4: f = y @ W_out -> single fp16 (K=DINNER, no wrap)
    tgbig_k<128, 0, 3, false><<<dim3(DMODEL / 128, NTOK / 128), 128, SMEM_B128>>>(
        pAy, pBwout, nullptr, nullptr, pAf, nullptr, NTOK, DMODEL, DINNER, nullptr, nullptr);
    // 7) G5: h1 = relu(f @ W1 + b1) -> single fp16 (K=DMODEL)
    tgsm_k<64, false, 1, 2><<<dim3(512 / 128, NTOK / 64), 256, SMEM_B64>>>(
        pAf, pBw1, b1, nullptr, pAh1, NTOK, 512, DMODEL, 0);
    // 8) G6+head fused
    tgfinal_k<<<dim3(1, NTOK / 64), 256, SMEM_FIN>>>(
        pAh1, pBw2, b2, W3, b3, out);
}